// round 7
// baseline (speedup 1.0000x reference)
#include <cuda_runtime.h>
#include <math.h>

#define N_NODES  100000
#define N_EDGES  1600000
#define NG       64
#define F0       32
#define F1       16
#define F2       8
#define NC       6
#define CAP      128          // ELL capacity; Poisson(16) => P(deg>128) ~ 0

// ---------------- scratch (device globals) ----------------------------------
__device__ int   g_deg[N_NODES];
__device__ int   g_ell[(size_t)N_NODES * CAP];   // 51.2 MB ELL src lists
__device__ float g_h1 [N_NODES * F1];            // relu(mlp1 output)
__device__ float g_pool[NG * F2];
__device__ float g_cnt[NG];

// ---------------- kernels ---------------------------------------------------

__global__ void k_zero() {
    int i = blockIdx.x * blockDim.x + threadIdx.x;
    if (i < N_NODES) g_deg[i] = 0;
    if (i < NG * F2) g_pool[i] = 0.f;
    if (i < NG)      g_cnt[i]  = 0.f;
}

// single pass: cursor-increment + ELL scatter
__global__ void k_fill(const int* __restrict__ src, const int* __restrict__ dst) {
    int e = blockIdx.x * blockDim.x + threadIdx.x;
    if (e < N_EDGES) {
        int d = dst[e];
        int p = atomicAdd(&g_deg[d], 1);
        if (p < CAP) g_ell[(size_t)d * CAP + p] = src[e];
    }
}

// ===== fused: gather1 (warp/node) + MLP1 (lane-parallel) =====================
// block = 256 threads = 8 warps = 8 nodes
__global__ void k_g1m1(const float* __restrict__ x,
                       const float* __restrict__ W1a, const float* __restrict__ b1a,
                       const float* __restrict__ W1b, const float* __restrict__ b1b) {
    __shared__ float sWa[F0 * 17];     // [f][j], stride 17 (conflict-free halves)
    __shared__ float sWb[F1 * 17];     // [k][j], stride 17
    __shared__ float sba[F1], sbb[F1];
    __shared__ float sh[8][F0 + 1];    // h0 per warp-node
    __shared__ float st[8][F1 + 1];    // relu(layer1) per warp-node

    int tid  = threadIdx.x;
    int wid  = tid >> 5;
    int lane = tid & 31;

    for (int i = tid; i < F0 * F1; i += blockDim.x) {
        int f = i >> 4, j = i & 15;
        sWa[f * 17 + j] = W1a[i];
    }
    for (int i = tid; i < F1 * F1; i += blockDim.x) {
        int k = i >> 4, j = i & 15;
        sWb[k * 17 + j] = W1b[i];
    }
    if (tid < F1) { sba[tid] = b1a[tid]; sbb[tid] = b1b[tid]; }
    __syncthreads();

    int w = blockIdx.x * 8 + wid;
    if (w >= N_NODES) return;

    // ---- gather: lane owns feature `lane`
    int deg = g_deg[w];
    if (deg > CAP) deg = CAP;
    const int* el = g_ell + (size_t)w * CAP;
    float acc = x[w * F0 + lane];
    int e = 0;
    for (; e + 8 <= deg; e += 8) {
        int4 a = *(const int4*)(el + e);
        int4 b = *(const int4*)(el + e + 4);
        float v0 = __ldg(&x[a.x * F0 + lane]);
        float v1 = __ldg(&x[a.y * F0 + lane]);
        float v2 = __ldg(&x[a.z * F0 + lane]);
        float v3 = __ldg(&x[a.w * F0 + lane]);
        float v4 = __ldg(&x[b.x * F0 + lane]);
        float v5 = __ldg(&x[b.y * F0 + lane]);
        float v6 = __ldg(&x[b.z * F0 + lane]);
        float v7 = __ldg(&x[b.w * F0 + lane]);
        acc += ((v0 + v1) + (v2 + v3)) + ((v4 + v5) + (v6 + v7));
    }
    if (e + 4 <= deg) {
        int4 a = *(const int4*)(el + e);
        acc += (__ldg(&x[a.x * F0 + lane]) + __ldg(&x[a.y * F0 + lane]))
             + (__ldg(&x[a.z * F0 + lane]) + __ldg(&x[a.w * F0 + lane]));
        e += 4;
    }
    for (; e < deg; ++e) acc += __ldg(&x[__ldg(&el[e]) * F0 + lane]);

    sh[wid][lane] = acc;
    __syncwarp();

    // ---- layer 1: 32->16, split f-range across halves
    int j    = lane & 15;
    int half = lane >> 4;
    int fb   = half * 16;
    float part = 0.f;
#pragma unroll
    for (int f = 0; f < 16; ++f)
        part += sh[wid][fb + f] * sWa[(fb + f) * 17 + j];
    part += __shfl_down_sync(0xffffffffu, part, 16);
    if (lane < F1) st[wid][j] = fmaxf(part + sba[j], 0.f);
    __syncwarp();

    // ---- layer 2: 16->16, split k-range across halves; outer relu fused
    part = 0.f;
#pragma unroll
    for (int k = 0; k < 8; ++k)
        part += st[wid][half * 8 + k] * sWb[(half * 8 + k) * 17 + j];
    part += __shfl_down_sync(0xffffffffu, part, 16);
    if (lane < F1) g_h1[w * F1 + j] = fmaxf(part + sbb[j], 0.f);
}

// ===== fused: gather2 (warp/node) + MLP2 + pool ==============================
// block = 256 threads = 8 warps = 8 nodes
__global__ void k_g2m2p(const float* __restrict__ W2a, const float* __restrict__ b2a,
                        const float* __restrict__ W2b, const float* __restrict__ b2b,
                        const int* __restrict__ batch) {
    __shared__ float sWa[F1 * F2], sWb[F2 * F2];
    __shared__ float sba[F2], sbb[F2];
    __shared__ float sh[8][F1 + 1];    // h1 + agg per warp-node
    __shared__ float st[8][F2 + 1];    // relu(layer1)
    __shared__ float sp[NG * F2];
    __shared__ float sc[NG];

    int tid  = threadIdx.x;
    int wid  = tid >> 5;
    int lane = tid & 31;

    for (int i = tid; i < F1 * F2; i += blockDim.x) sWa[i] = W2a[i];
    for (int i = tid; i < F2 * F2; i += blockDim.x) sWb[i] = W2b[i];
    if (tid < F2) { sba[tid] = b2a[tid]; sbb[tid] = b2b[tid]; }
    for (int i = tid; i < NG * F2; i += blockDim.x) sp[i] = 0.f;
    for (int i = tid; i < NG;      i += blockDim.x) sc[i] = 0.f;
    __syncthreads();

    int w = blockIdx.x * 8 + wid;
    if (w < N_NODES) {
        // ---- gather: 16-float rows, two edges in flight per step
        int f    = lane & 15;
        int half = lane >> 4;
        int deg  = g_deg[w];
        if (deg > CAP) deg = CAP;
        const int* el = g_ell + (size_t)w * CAP;
        float acc = 0.f;
        int e = 0;
        for (; e + 8 <= deg; e += 8) {
            int4 a = *(const int4*)(el + e);
            int4 b = *(const int4*)(el + e + 4);
            int s0 = half ? a.y : a.x;
            int s1 = half ? a.w : a.z;
            int s2 = half ? b.y : b.x;
            int s3 = half ? b.w : b.z;
            float v0 = __ldg(&g_h1[s0 * F1 + f]);
            float v1 = __ldg(&g_h1[s1 * F1 + f]);
            float v2 = __ldg(&g_h1[s2 * F1 + f]);
            float v3 = __ldg(&g_h1[s3 * F1 + f]);
            acc += (v0 + v1) + (v2 + v3);
        }
        for (; e + 2 <= deg; e += 2) {
            int s = __ldg(&el[e + half]);
            acc += __ldg(&g_h1[s * F1 + f]);
        }
        if (e < deg && half == 0) {
            int s = __ldg(&el[e]);
            acc += __ldg(&g_h1[s * F1 + f]);
        }
        acc += __shfl_down_sync(0xffffffffu, acc, 16);
        if (lane < F1) sh[wid][f] = g_h1[w * F1 + f] + acc;
        __syncwarp();

        // ---- MLP2 on lanes 0..7: 16 -> relu(8) -> relu(8)
        if (lane < F2) {
            float t = sba[lane];
#pragma unroll
            for (int ff = 0; ff < F1; ++ff)
                t += sh[wid][ff] * sWa[ff * F2 + lane];
            st[wid][lane] = fmaxf(t, 0.f);
        }
        __syncwarp();
        if (lane < F2) {
            float o = sbb[lane];
#pragma unroll
            for (int k = 0; k < F2; ++k)
                o += st[wid][k] * sWb[k * F2 + lane];
            o = fmaxf(o, 0.f);
            int b = batch[w];
            atomicAdd(&sp[b * F2 + lane], o);
            if (lane == 0) atomicAdd(&sc[b], 1.f);
        }
    }
    __syncthreads();
    for (int i = tid; i < NG * F2; i += blockDim.x)
        if (sp[i] != 0.f) atomicAdd(&g_pool[i], sp[i]);
    for (int i = tid; i < NG; i += blockDim.x)
        if (sc[i] != 0.f) atomicAdd(&g_cnt[i], sc[i]);
}

__global__ void k_head(const float* __restrict__ Wfc, const float* __restrict__ bfc,
                       float* __restrict__ out) {
    int g = threadIdx.x;
    if (g >= NG) return;
    float c = g_cnt[g];
    c = (c < 1.f) ? 1.f : c;
    float p[F2];
#pragma unroll
    for (int j = 0; j < F2; ++j) p[j] = g_pool[g * F2 + j] / c;
    float l[NC];
#pragma unroll
    for (int j = 0; j < NC; ++j) {
        float a = bfc[j];
#pragma unroll
        for (int f = 0; f < F2; ++f) a += p[f] * Wfc[f * NC + j];
        l[j] = a;
    }
    float m = l[0];
#pragma unroll
    for (int j = 1; j < NC; ++j) m = fmaxf(m, l[j]);
    float s = 0.f;
#pragma unroll
    for (int j = 0; j < NC; ++j) s += expf(l[j] - m);
    float ls = logf(s);
#pragma unroll
    for (int j = 0; j < NC; ++j) out[g * NC + j] = l[j] - m - ls;
}

// ---------------- launch ----------------------------------------------------

extern "C" void kernel_launch(void* const* d_in, const int* in_sizes, int n_in,
                              void* d_out, int out_size) {
    const float* x   = (const float*)d_in[0];
    const int*   ei  = (const int*)d_in[1];     // [2, E] int32
    const int*   bat = (const int*)d_in[2];     // int32
    const float* W1a = (const float*)d_in[3];
    const float* b1a = (const float*)d_in[4];
    const float* W1b = (const float*)d_in[5];
    const float* b1b = (const float*)d_in[6];
    const float* W2a = (const float*)d_in[7];
    const float* b2a = (const float*)d_in[8];
    const float* W2b = (const float*)d_in[9];
    const float* b2b = (const float*)d_in[10];
    const float* Wfc = (const float*)d_in[11];
    const float* bfc = (const float*)d_in[12];
    float* out = (float*)d_out;

    const int* src = ei;
    const int* dst = ei + N_EDGES;

    const int BS = 256;
    int gb_nodes = (N_NODES + BS - 1) / BS;
    int gb_edges = (N_EDGES + BS - 1) / BS;
    int gb_warp8 = (N_NODES + 7) / 8;          // 8 nodes per 256-thread block

    k_zero  <<<gb_nodes, BS>>>();
    k_fill  <<<gb_edges, BS>>>(src, dst);
    k_g1m1  <<<gb_warp8, BS>>>(x, W1a, b1a, W1b, b1b);
    k_g2m2p <<<gb_warp8, BS>>>(W2a, b2a, W2b, b2b, bat);
    k_head  <<<1, 64>>>(Wfc, bfc, out);
}

// round 8
// speedup vs baseline: 1.2146x; 1.2146x over previous
#include <cuda_runtime.h>
#include <math.h>

#define N_NODES  100000
#define N_EDGES  1600000
#define NG       64
#define F0       32
#define F1       16
#define F2       8
#define NC       6
#define CAP      128          // ELL capacity; Poisson(16) => P(deg>128) ~ 0
#define GRID_P   1184         // persistent grid: 8 blocks/SM * 148 SMs

// ---------------- scratch (device globals) ----------------------------------
__device__ int   g_deg[N_NODES];
__device__ int   g_ell[(size_t)N_NODES * CAP];   // 51.2 MB ELL src lists
__device__ float g_h1 [N_NODES * F1];            // relu(mlp1 output)
__device__ float g_pool[NG * F2];
__device__ float g_cnt[NG];

// ---------------- kernels ---------------------------------------------------

__global__ void k_zero() {
    int i = blockIdx.x * blockDim.x + threadIdx.x;
    if (i < N_NODES) g_deg[i] = 0;
    if (i < NG * F2) g_pool[i] = 0.f;
    if (i < NG)      g_cnt[i]  = 0.f;
}

// single pass: cursor-increment + ELL scatter
__global__ void k_fill(const int* __restrict__ src, const int* __restrict__ dst) {
    int e = blockIdx.x * blockDim.x + threadIdx.x;
    if (e < N_EDGES) {
        int d = dst[e];
        int p = atomicAdd(&g_deg[d], 1);
        if (p < CAP) g_ell[(size_t)d * CAP + p] = src[e];
    }
}

// ===== fused gather1 + MLP1, persistent, float4 gather =======================
// block = 256 = 8 warps; warp w handles nodes blockIdx*8+wid, step gridDim*8
__global__ void __launch_bounds__(256, 8)
k_g1m1(const float* __restrict__ x,
       const float* __restrict__ W1a, const float* __restrict__ b1a,
       const float* __restrict__ W1b, const float* __restrict__ b1b) {
    __shared__ float sWa[F0 * 17];     // [f][j] stride 17 (conflict-free halves)
    __shared__ float sWb[F1 * 17];
    __shared__ float sba[F1], sbb[F1];
    __shared__ float sh[8][F0];        // h0 per warp-node (128B rows, f4-aligned)
    __shared__ float st[8][F1];

    int tid  = threadIdx.x;
    int wid  = tid >> 5;
    int lane = tid & 31;

    for (int i = tid; i < F0 * F1; i += 256) sWa[(i >> 4) * 17 + (i & 15)] = W1a[i];
    for (int i = tid; i < F1 * F1; i += 256) sWb[(i >> 4) * 17 + (i & 15)] = W1b[i];
    if (tid < F1) { sba[tid] = b1a[tid]; sbb[tid] = b1b[tid]; }
    __syncthreads();

    int slot = lane >> 3;      // 0..3 : edge slot
    int q    = lane & 7;       // 0..7 : row quarter (float4)
    int j    = lane & 15;
    int half = lane >> 4;

    for (int w = blockIdx.x * 8 + wid; w < N_NODES; w += GRID_P * 8) {
        int deg = g_deg[w];
        if (deg > CAP) deg = CAP;
        const int* el = g_ell + (size_t)w * CAP;

        float4 a4 = make_float4(0.f, 0.f, 0.f, 0.f);
        int e = 0;
        for (; e + 4 <= deg; e += 4) {
            int s = __ldg(&el[e + slot]);                       // broadcast x4
            float4 v = __ldg((const float4*)(x + s * F0) + q);  // 512B/warp
            a4.x += v.x; a4.y += v.y; a4.z += v.z; a4.w += v.w;
        }
        int rem = deg - e;
        if (slot < rem) {
            int s = __ldg(&el[e + slot]);
            float4 v = __ldg((const float4*)(x + s * F0) + q);
            a4.x += v.x; a4.y += v.y; a4.z += v.z; a4.w += v.w;
        }
        // reduce across 4 slots (lanes q, q+8, q+16, q+24)
#pragma unroll
        for (int off = 16; off >= 8; off >>= 1) {
            a4.x += __shfl_down_sync(0xffffffffu, a4.x, off);
            a4.y += __shfl_down_sync(0xffffffffu, a4.y, off);
            a4.z += __shfl_down_sync(0xffffffffu, a4.z, off);
            a4.w += __shfl_down_sync(0xffffffffu, a4.w, off);
        }
        if (lane < 8) {                                  // self term + store h0
            float4 xs = __ldg((const float4*)(x + w * F0) + q);
            a4.x += xs.x; a4.y += xs.y; a4.z += xs.z; a4.w += xs.w;
            ((float4*)sh[wid])[q] = a4;
        }
        __syncwarp();

        // layer 1: 32->16, f-range split across halves
        int fb = half * 16;
        float part = 0.f;
#pragma unroll
        for (int f = 0; f < 16; ++f)
            part += sh[wid][fb + f] * sWa[(fb + f) * 17 + j];
        part += __shfl_down_sync(0xffffffffu, part, 16);
        if (lane < F1) st[wid][j] = fmaxf(part + sba[j], 0.f);
        __syncwarp();

        // layer 2: 16->16, k-range split; outer relu fused
        part = 0.f;
#pragma unroll
        for (int k = 0; k < 8; ++k)
            part += st[wid][half * 8 + k] * sWb[(half * 8 + k) * 17 + j];
        part += __shfl_down_sync(0xffffffffu, part, 16);
        if (lane < F1) g_h1[w * F1 + j] = fmaxf(part + sbb[j], 0.f);
        __syncwarp();
    }
}

// ===== fused gather2 + MLP2 + pool, persistent, float4 gather ================
__global__ void __launch_bounds__(256, 8)
k_g2m2p(const float* __restrict__ W2a, const float* __restrict__ b2a,
        const float* __restrict__ W2b, const float* __restrict__ b2b,
        const int* __restrict__ batch) {
    __shared__ float sWa[F1 * F2], sWb[F2 * F2];
    __shared__ float sba[F2], sbb[F2];
    __shared__ float sh[8][F1];        // h1+agg per warp-node (64B, f4-aligned)
    __shared__ float st[8][F2];
    __shared__ float sp[NG * F2];
    __shared__ float sc[NG];

    int tid  = threadIdx.x;
    int wid  = tid >> 5;
    int lane = tid & 31;

    for (int i = tid; i < F1 * F2; i += 256) sWa[i] = W2a[i];
    for (int i = tid; i < F2 * F2; i += 256) sWb[i] = W2b[i];
    if (tid < F2) { sba[tid] = b2a[tid]; sbb[tid] = b2b[tid]; }
    for (int i = tid; i < NG * F2; i += 256) sp[i] = 0.f;
    for (int i = tid; i < NG;      i += 256) sc[i] = 0.f;
    __syncthreads();

    int slot = lane >> 2;      // 0..7 : edge slot
    int q    = lane & 3;       // 0..3 : row quarter (float4)

    for (int w = blockIdx.x * 8 + wid; w < N_NODES; w += GRID_P * 8) {
        int deg = g_deg[w];
        if (deg > CAP) deg = CAP;
        const int* el = g_ell + (size_t)w * CAP;

        float4 a4 = make_float4(0.f, 0.f, 0.f, 0.f);
        int e = 0;
        for (; e + 8 <= deg; e += 8) {
            int s = __ldg(&el[e + slot]);                         // broadcast x4
            float4 v = __ldg((const float4*)(g_h1 + s * F1) + q); // 512B/warp
            a4.x += v.x; a4.y += v.y; a4.z += v.z; a4.w += v.w;
        }
        int rem = deg - e;
        if (slot < rem) {
            int s = __ldg(&el[e + slot]);
            float4 v = __ldg((const float4*)(g_h1 + s * F1) + q);
            a4.x += v.x; a4.y += v.y; a4.z += v.z; a4.w += v.w;
        }
        // reduce across 8 slots (lanes q, q+4, ..., q+28)
#pragma unroll
        for (int off = 16; off >= 4; off >>= 1) {
            a4.x += __shfl_down_sync(0xffffffffu, a4.x, off);
            a4.y += __shfl_down_sync(0xffffffffu, a4.y, off);
            a4.z += __shfl_down_sync(0xffffffffu, a4.z, off);
            a4.w += __shfl_down_sync(0xffffffffu, a4.w, off);
        }
        if (lane < 4) {                                  // self term + store
            float4 hs = __ldg((const float4*)(g_h1 + w * F1) + q);
            a4.x += hs.x; a4.y += hs.y; a4.z += hs.z; a4.w += hs.w;
            ((float4*)sh[wid])[q] = a4;
        }
        __syncwarp();

        // MLP2 on lanes 0..7: 16 -> relu(8) -> relu(8)
        if (lane < F2) {
            float t = sba[lane];
#pragma unroll
            for (int f = 0; f < F1; ++f)
                t += sh[wid][f] * sWa[f * F2 + lane];
            st[wid][lane] = fmaxf(t, 0.f);
        }
        __syncwarp();
        if (lane < F2) {
            float o = sbb[lane];
#pragma unroll
            for (int k = 0; k < F2; ++k)
                o += st[wid][k] * sWb[k * F2 + lane];
            o = fmaxf(o, 0.f);
            int b = __ldg(&batch[w]);
            atomicAdd(&sp[b * F2 + lane], o);
            if (lane == 0) atomicAdd(&sc[b], 1.f);
        }
        __syncwarp();
    }

    __syncthreads();
    for (int i = tid; i < NG * F2; i += 256)
        if (sp[i] != 0.f) atomicAdd(&g_pool[i], sp[i]);
    for (int i = tid; i < NG; i += 256)
        if (sc[i] != 0.f) atomicAdd(&g_cnt[i], sc[i]);
}

__global__ void k_head(const float* __restrict__ Wfc, const float* __restrict__ bfc,
                       float* __restrict__ out) {
    int g = threadIdx.x;
    if (g >= NG) return;
    float c = g_cnt[g];
    c = (c < 1.f) ? 1.f : c;
    float p[F2];
#pragma unroll
    for (int j = 0; j < F2; ++j) p[j] = g_pool[g * F2 + j] / c;
    float l[NC];
#pragma unroll
    for (int j = 0; j < NC; ++j) {
        float a = bfc[j];
#pragma unroll
        for (int f = 0; f < F2; ++f) a += p[f] * Wfc[f * NC + j];
        l[j] = a;
    }
    float m = l[0];
#pragma unroll
    for (int j = 1; j < NC; ++j) m = fmaxf(m, l[j]);
    float s = 0.f;
#pragma unroll
    for (int j = 0; j < NC; ++j) s += expf(l[j] - m);
    float ls = logf(s);
#pragma unroll
    for (int j = 0; j < NC; ++j) out[g * NC + j] = l[j] - m - ls;
}

// ---------------- launch ----------------------------------------------------

extern "C" void kernel_launch(void* const* d_in, const int* in_sizes, int n_in,
                              void* d_out, int out_size) {
    const float* x   = (const float*)d_in[0];
    const int*   ei  = (const int*)d_in[1];     // [2, E] int32
    const int*   bat = (const int*)d_in[2];     // int32
    const float* W1a = (const float*)d_in[3];
    const float* b1a = (const float*)d_in[4];
    const float* W1b = (const float*)d_in[5];
    const float* b1b = (const float*)d_in[6];
    const float* W2a = (const float*)d_in[7];
    const float* b2a = (const float*)d_in[8];
    const float* W2b = (const float*)d_in[9];
    const float* b2b = (const float*)d_in[10];
    const float* Wfc = (const float*)d_in[11];
    const float* bfc = (const float*)d_in[12];
    float* out = (float*)d_out;

    const int* src = ei;
    const int* dst = ei + N_EDGES;

    const int BS = 256;
    int gb_nodes = (N_NODES + BS - 1) / BS;
    int gb_edges = (N_EDGES + BS - 1) / BS;

    k_zero  <<<gb_nodes, BS>>>();
    k_fill  <<<gb_edges, BS>>>(src, dst);
    k_g1m1  <<<GRID_P, BS>>>(x, W1a, b1a, W1b, b1b);
    k_g2m2p <<<GRID_P, BS>>>(W2a, b2a, W2b, b2b, bat);
    k_head  <<<1, 64>>>(Wfc, bfc, out);
}